// round 8
// baseline (speedup 1.0000x reference)
#include <cuda_runtime.h>
#include <cuda_fp16.h>
#include <math.h>
#include <stdint.h>

#define S_LEN   4096
#define DMODEL  1024
#define NHEADS  16
#define HDIM    64

// Scratch (allocation-free rule: device globals)
__device__ __half g_Qh[S_LEN * DMODEL];              // [s][d] fp16
__device__ __half g_Kh[S_LEN * DMODEL];              // [s][d] fp16
__device__ __half g_VT[NHEADS * HDIM * S_LEN];       // [h][d][s] fp16
__device__ float  g_A [S_LEN * DMODEL];              // attention out fp32

// ---------------------------------------------------------------------------
// Helpers
// ---------------------------------------------------------------------------
__device__ __forceinline__ uint32_t pack_f16(float lo, float hi) {
    __half2 h = __floats2half2_rn(lo, hi);
    return *(uint32_t*)&h;
}

__device__ __forceinline__ void mma16(float* c,
    uint32_t a0, uint32_t a1, uint32_t a2, uint32_t a3,
    uint32_t b0, uint32_t b1)
{
    asm volatile(
        "mma.sync.aligned.m16n8k16.row.col.f32.f16.f16.f32 "
        "{%0,%1,%2,%3}, {%4,%5,%6,%7}, {%8,%9}, {%0,%1,%2,%3};"
        : "+f"(c[0]), "+f"(c[1]), "+f"(c[2]), "+f"(c[3])
        : "r"(a0), "r"(a1), "r"(a2), "r"(a3), "r"(b0), "r"(b1));
}

// ---------------------------------------------------------------------------
// FP16 GEMM body (fp32 in, fp16 compute, fp32 accum).
// BM=128 BN=128 BK=16, 256 thr, 8 warps 2x4, warp tile 64m x 32n.
// As: [128 rows][8 k-pairs] u32 stride 12; Bs: [128 n][8 k-pairs] u32 stride 12.
// mode: 0 = fp16 natural out, 2 = fp16 transposed [d][s] out, 3 = fp32 out.
// ---------------------------------------------------------------------------
#define GBK 16
#define SAH 12
#define SBH 12

__device__ __forceinline__ void gemm_body(
    const float* __restrict__ A, const float* __restrict__ W,
    const float* __restrict__ bias,
    float* __restrict__ Cf, __half* __restrict__ Ch,
    int N, int K, int bx, int by, int mode)
{
    __shared__ uint32_t As[128 * SAH];   // 6 KB
    __shared__ uint32_t Bs[128 * SBH];   // 6 KB

    const int tid = threadIdx.x;
    const int lane = tid & 31;
    const int w = tid >> 5;
    const int wm = (w >> 2) * 64;
    const int wn = (w & 3) * 32;
    const int gid = lane >> 2;
    const int tig = lane & 3;

    const float* Ag = A + (size_t)by * 128 * K;
    const float* Wg = W + bx * 128;

    // A loader: thread covers row ar, k-range [akh, akh+8)
    const int ar  = tid >> 1;
    const int akh = (tid & 1) * 8;
    // B loader: thread covers column bn, k-range [bkh, bkh+8)
    const int bn  = tid & 127;
    const int bkh = (tid >> 7) * 8;

    float4 ra0, ra1;
    float rb[8];

    float acc[4][4][4];
#pragma unroll
    for (int mt = 0; mt < 4; mt++)
#pragma unroll
        for (int nt = 0; nt < 4; nt++)
#pragma unroll
            for (int e = 0; e < 4; e++) acc[mt][nt][e] = 0.f;

#define LOADG(k0) do { \
        ra0 = *(const float4*)(Ag + (size_t)ar * K + (k0) + akh); \
        ra1 = *(const float4*)(Ag + (size_t)ar * K + (k0) + akh + 4); \
        _Pragma("unroll") \
        for (int i = 0; i < 8; i++) \
            rb[i] = Wg[(size_t)((k0) + bkh + i) * N + bn]; \
    } while (0)

#define STORES() do { \
        uint4 pa; \
        pa.x = pack_f16(ra0.x, ra0.y); pa.y = pack_f16(ra0.z, ra0.w); \
        pa.z = pack_f16(ra1.x, ra1.y); pa.w = pack_f16(ra1.z, ra1.w); \
        *(uint4*)&As[ar * SAH + akh / 2] = pa; \
        uint4 pb; \
        pb.x = pack_f16(rb[0], rb[1]); pb.y = pack_f16(rb[2], rb[3]); \
        pb.z = pack_f16(rb[4], rb[5]); pb.w = pack_f16(rb[6], rb[7]); \
        *(uint4*)&Bs[bn * SBH + bkh / 2] = pb; \
    } while (0)

    const int NIT = K / GBK;
    LOADG(0);
    STORES();
    __syncthreads();

    for (int it = 0; it < NIT; it++) {
        if (it + 1 < NIT) LOADG((it + 1) * GBK);

        uint32_t b[4][2];
#pragma unroll
        for (int nt = 0; nt < 4; nt++) {
            b[nt][0] = Bs[(wn + nt * 8 + gid) * SBH + tig];
            b[nt][1] = Bs[(wn + nt * 8 + gid) * SBH + tig + 4];
        }
#pragma unroll
        for (int mt = 0; mt < 4; mt++) {
            int r = wm + mt * 16 + gid;
            uint32_t a0 = As[r * SAH + tig];
            uint32_t a1 = As[(r + 8) * SAH + tig];
            uint32_t a2 = As[r * SAH + tig + 4];
            uint32_t a3 = As[(r + 8) * SAH + tig + 4];
#pragma unroll
            for (int nt = 0; nt < 4; nt++)
                mma16(acc[mt][nt], a0, a1, a2, a3, b[nt][0], b[nt][1]);
        }
        __syncthreads();
        if (it + 1 < NIT) {
            STORES();
            __syncthreads();
        }
    }

    // epilogue
#pragma unroll
    for (int nt = 0; nt < 4; nt++) {
        int col = bx * 128 + wn + nt * 8 + 2 * tig;
        float b0 = bias[col], b1 = bias[col + 1];
#pragma unroll
        for (int mt = 0; mt < 4; mt++) {
            int row = by * 128 + wm + mt * 16 + gid;
            float c0 = acc[mt][nt][0] + b0;
            float c1 = acc[mt][nt][1] + b1;
            float c2 = acc[mt][nt][2] + b0;
            float c3 = acc[mt][nt][3] + b1;
            if (mode == 3) {
                float2 o;
                o.x = c0; o.y = c1;
                *(float2*)(&Cf[(size_t)row * N + col]) = o;
                o.x = c2; o.y = c3;
                *(float2*)(&Cf[(size_t)(row + 8) * N + col]) = o;
            } else if (mode == 2) {
                // V transposed fp16: VT[col][row], row length = S_LEN
                Ch[(size_t)col * S_LEN + row]           = __float2half_rn(c0);
                Ch[(size_t)(col + 1) * S_LEN + row]     = __float2half_rn(c1);
                Ch[(size_t)col * S_LEN + row + 8]       = __float2half_rn(c2);
                Ch[(size_t)(col + 1) * S_LEN + row + 8] = __float2half_rn(c3);
            } else {
                uint32_t* Cp = (uint32_t*)Ch;
                Cp[(size_t)row * (N / 2) + (col >> 1)]       = pack_f16(c0, c1);
                Cp[(size_t)(row + 8) * (N / 2) + (col >> 1)] = pack_f16(c2, c3);
            }
        }
    }
#undef LOADG
#undef STORES
}

// Fused Q/K/V projection: blockIdx.z selects which projection.
__global__ __launch_bounds__(256) void gemm_qkv(
    const float* __restrict__ q_in, const float* __restrict__ k_in,
    const float* __restrict__ v_in,
    const float* __restrict__ Wq, const float* __restrict__ bq,
    const float* __restrict__ Wk, const float* __restrict__ bk,
    const float* __restrict__ Wv, const float* __restrict__ bv,
    __half* __restrict__ Qo, __half* __restrict__ Ko,
    __half* __restrict__ Vo)
{
    if (blockIdx.z == 0)
        gemm_body(q_in, Wq, bq, nullptr, Qo, DMODEL, DMODEL, blockIdx.x, blockIdx.y, 0);
    else if (blockIdx.z == 1)
        gemm_body(k_in, Wk, bk, nullptr, Ko, DMODEL, DMODEL, blockIdx.x, blockIdx.y, 0);
    else
        gemm_body(v_in, Wv, bv, nullptr, Vo, DMODEL, DMODEL, blockIdx.x, blockIdx.y, 2);
}

__global__ __launch_bounds__(256) void gemm_out(
    const float* __restrict__ A, const float* __restrict__ W,
    const float* __restrict__ bias, float* __restrict__ C)
{
    gemm_body(A, W, bias, C, nullptr, DMODEL, DMODEL, blockIdx.x, blockIdx.y, 3);
}

// ---------------------------------------------------------------------------
// fp16 flash attention: 256 threads, 8 warps, CTA = 128 q-rows.
// Warp owns 16 q-rows x all 64 key cols (warp-local softmax).
// All operands fp16 (m16n8k16), fp32 accumulate. V pre-transposed [h][d][s].
// Smem strides 36 u32/row -> all fragment accesses are 32-bank bijections.
// ---------------------------------------------------------------------------
#define US 36

__global__ __launch_bounds__(256, 2) void attn_f16(
    const __half* __restrict__ Qh, const __half* __restrict__ Kh,
    const __half* __restrict__ VTh, const int* __restrict__ mask,
    float* __restrict__ O)
{
    extern __shared__ uint32_t smu[];
    uint32_t* QPs = smu;                 // 128*36 u32  (Q staging, then P)
    uint32_t* Ks  = QPs + 128 * US;      // 64*36
    uint32_t* Vs  = Ks + 64 * US;        // 64*36  (V^T tile: rows=d, k-pairs)
    float*    ms  = (float*)(Vs + 64 * US);  // 64

    const int h   = blockIdx.x;
    const int qb  = blockIdx.y;
    const int tid = threadIdx.x;
    const int lane = tid & 31;
    const int w = tid >> 5;
    const int wbase = w * 16;
    const int gid = lane >> 2;
    const int tig = lane & 3;
    const int r0 = wbase + gid;          // owned rows: r0, r0+8

    const float LOG2E = 1.4426950408889634f;
    const float SCALE = 0.125f * LOG2E;

    const uint32_t* Qg = (const uint32_t*)Qh;
    const uint32_t* Kg = (const uint32_t*)Kh;
    const uint32_t* Vg = (const uint32_t*)VTh;

    // ---- Stage Q tile (128 rows x 32 u32) ----
#pragma unroll
    for (int it = 0; it < 4; it++) {
        int lin = it * 256 + tid;            // 0..1023 uint4 slots
        int row = lin >> 3, q4 = (lin & 7) * 4;
        *(uint4*)&QPs[row * US + q4] =
            *(const uint4*)(Qg + (size_t)(qb * 128 + row) * (DMODEL / 2) + h * 32 + q4);
    }
    __syncthreads();

    // ---- Hoist Q fragments (4 k16-chunks x 4 regs) ----
    uint32_t q[4][4];
#pragma unroll
    for (int c = 0; c < 4; c++) {
        q[c][0] = QPs[r0 * US + c * 8 + tig];
        q[c][1] = QPs[(r0 + 8) * US + c * 8 + tig];
        q[c][2] = QPs[r0 * US + c * 8 + tig + 4];
        q[c][3] = QPs[(r0 + 8) * US + c * 8 + tig + 4];
    }
    // QPs now reused as P staging; each warp touches only its own 16 rows.

    float o[8][4];
    float m0 = -1e30f, m1 = -1e30f, l0 = 0.f, l1 = 0.f;
#pragma unroll
    for (int nt = 0; nt < 8; nt++)
#pragma unroll
        for (int e = 0; e < 4; e++) o[nt][e] = 0.f;

    for (int kb = 0; kb < S_LEN / 64; kb++) {
        __syncthreads();   // previous tile fully consumed
#pragma unroll
        for (int it = 0; it < 2; it++) {
            int lin = it * 256 + tid;        // 0..511 uint4 slots
            int row = lin >> 3, q4 = (lin & 7) * 4;
            *(uint4*)&Ks[row * US + q4] =
                *(const uint4*)(Kg + (size_t)(kb * 64 + row) * (DMODEL / 2) + h * 32 + q4);
            *(uint4*)&Vs[row * US + q4] =
                *(const uint4*)(Vg + (size_t)(h * HDIM + row) * (S_LEN / 2) + kb * 32 + q4);
        }
        if (tid < 64) ms[tid] = (mask[kb * 64 + tid] == 0) ? -1.0e9f * LOG2E : 0.f;
        __syncthreads();

        // ---- S = Q @ K^T : 16 rows x 64 cols per warp ----
        float s[8][4];
#pragma unroll
        for (int nt = 0; nt < 8; nt++)
#pragma unroll
            for (int e = 0; e < 4; e++) s[nt][e] = 0.f;

#pragma unroll
        for (int c = 0; c < 4; c++) {
#pragma unroll
            for (int nt = 0; nt < 8; nt++) {
                int kr = nt * 8 + gid;
                uint32_t b0 = Ks[kr * US + c * 8 + tig];
                uint32_t b1 = Ks[kr * US + c * 8 + tig + 4];
                mma16(s[nt], q[c][0], q[c][1], q[c][2], q[c][3], b0, b1);
            }
        }

        // ---- warp-local online softmax (log2 domain) ----
        float mx0 = -1e30f, mx1 = -1e30f;
#pragma unroll
        for (int nt = 0; nt < 8; nt++) {
            int col = nt * 8 + 2 * tig;
            float mk0 = ms[col], mk1 = ms[col + 1];
            s[nt][0] = s[nt][0] * SCALE + mk0;
            s[nt][1] = s[nt][1] * SCALE + mk1;
            s[nt][2] = s[nt][2] * SCALE + mk0;
            s[nt][3] = s[nt][3] * SCALE + mk1;
            mx0 = fmaxf(mx0, fmaxf(s[nt][0], s[nt][1]));
            mx1 = fmaxf(mx1, fmaxf(s[nt][2], s[nt][3]));
        }
        mx0 = fmaxf(mx0, __shfl_xor_sync(0xffffffffu, mx0, 1));
        mx0 = fmaxf(mx0, __shfl_xor_sync(0xffffffffu, mx0, 2));
        mx1 = fmaxf(mx1, __shfl_xor_sync(0xffffffffu, mx1, 1));
        mx1 = fmaxf(mx1, __shfl_xor_sync(0xffffffffu, mx1, 2));

        float nm0 = fmaxf(m0, mx0);
        float nm1 = fmaxf(m1, mx1);
        float f0 = exp2f(m0 - nm0);
        float f1 = exp2f(m1 - nm1);
        m0 = nm0; m1 = nm1;

        float sum0 = 0.f, sum1 = 0.f;
#pragma unroll
        for (int nt = 0; nt < 8; nt++) {
            float p0 = exp2f(s[nt][0] - nm0);
            float p1 = exp2f(s[nt][1] - nm0);
            float p2 = exp2f(s[nt][2] - nm1);
            float p3 = exp2f(s[nt][3] - nm1);
            sum0 += p0 + p1; sum1 += p2 + p3;
            QPs[r0 * US + nt * 4 + tig]       = pack_f16(p0, p1);
            QPs[(r0 + 8) * US + nt * 4 + tig] = pack_f16(p2, p3);
            o[nt][0] *= f0; o[nt][1] *= f0;
            o[nt][2] *= f1; o[nt][3] *= f1;
        }
        sum0 += __shfl_xor_sync(0xffffffffu, sum0, 1);
        sum0 += __shfl_xor_sync(0xffffffffu, sum0, 2);
        sum1 += __shfl_xor_sync(0xffffffffu, sum1, 1);
        sum1 += __shfl_xor_sync(0xffffffffu, sum1, 2);
        l0 = l0 * f0 + sum0;
        l1 = l1 * f1 + sum1;
        __syncwarp();   // P rows warp-private: order stores before loads

        // ---- O += P @ V ----
#pragma unroll
        for (int c = 0; c < 4; c++) {
            uint32_t a0 = QPs[r0 * US + c * 8 + tig];
            uint32_t a1 = QPs[(r0 + 8) * US + c * 8 + tig];
            uint32_t a2 = QPs[r0 * US + c * 8 + tig + 4];
            uint32_t a3 = QPs[(r0 + 8) * US + c * 8 + tig + 4];
#pragma unroll
            for (int nt = 0; nt < 8; nt++) {
                int dc = nt * 8 + gid;
                uint32_t b0 = Vs[dc * US + c * 8 + tig];
                uint32_t b1 = Vs[dc * US + c * 8 + tig + 4];
                mma16(o[nt], a0, a1, a2, a3, b0, b1);
            }
        }
    }

    // ---- normalize + write fp32 ----
    float inv0 = 1.f / fmaxf(l0, 1e-20f);
    float inv1 = 1.f / fmaxf(l1, 1e-20f);
#pragma unroll
    for (int nt = 0; nt < 8; nt++) {
        int col = h * HDIM + nt * 8 + 2 * tig;
        float2 r;
        r.x = o[nt][0] * inv0; r.y = o[nt][1] * inv0;
        *(float2*)(&O[(size_t)(qb * 128 + r0) * DMODEL + col]) = r;
        r.x = o[nt][2] * inv1; r.y = o[nt][3] * inv1;
        *(float2*)(&O[(size_t)(qb * 128 + r0 + 8) * DMODEL + col]) = r;
    }
}

// ---------------------------------------------------------------------------
extern "C" void kernel_launch(void* const* d_in, const int* in_sizes, int n_in,
                              void* d_out, int out_size)
{
    (void)in_sizes; (void)n_in; (void)out_size;
    const float* query = (const float*)d_in[0];
    const float* key   = (const float*)d_in[1];
    const float* value = (const float*)d_in[2];
    const int*   amask = (const int*)  d_in[3];
    const float* Wq = (const float*)d_in[4];
    const float* bq = (const float*)d_in[5];
    const float* Wk = (const float*)d_in[6];
    const float* bk = (const float*)d_in[7];
    const float* Wv = (const float*)d_in[8];
    const float* bv = (const float*)d_in[9];
    const float* Wo = (const float*)d_in[10];
    const float* bo = (const float*)d_in[11];
    float* out = (float*)d_out;

    __half *Qhp, *Khp, *VTp;
    float *Ap;
    cudaGetSymbolAddress((void**)&Qhp, g_Qh);
    cudaGetSymbolAddress((void**)&Khp, g_Kh);
    cudaGetSymbolAddress((void**)&VTp, g_VT);
    cudaGetSymbolAddress((void**)&Ap,  g_A);

    // Fused Q/K/V projections (fp16 compute, fp16 output; V pre-transposed)
    gemm_qkv<<<dim3(DMODEL / 128, S_LEN / 128, 3), 256>>>(
        query, key, value, Wq, bq, Wk, bk, Wv, bv, Qhp, Khp, VTp);

    size_t smem = (size_t)(128 * US + 64 * US + 64 * US) * 4 + 64 * 4;  // ~36.5 KB
    attn_f16<<<dim3(NHEADS, S_LEN / 128), 256, smem>>>(Qhp, Khp, VTp, amask, Ap);

    gemm_out<<<dim3(DMODEL / 128, S_LEN / 128), 256>>>(Ap, Wo, bo, out);
}

// round 11
// speedup vs baseline: 1.3635x; 1.3635x over previous
#include <cuda_runtime.h>
#include <cuda_fp16.h>
#include <math.h>
#include <stdint.h>

#define S_LEN   4096
#define DMODEL  1024
#define NHEADS  16
#define HDIM    64

// Scratch (allocation-free rule: device globals)
__device__ __half g_Qh[S_LEN * DMODEL];              // [s][d] fp16
__device__ __half g_Kh[S_LEN * DMODEL];              // [s][d] fp16
__device__ __half g_VT[NHEADS * HDIM * S_LEN];       // [h][d][s] fp16
__device__ float  g_A [S_LEN * DMODEL];              // attention out fp32

// ---------------------------------------------------------------------------
// Helpers
// ---------------------------------------------------------------------------
__device__ __forceinline__ float to_tf32(float x) {
    float r;
    asm("cvt.rna.tf32.f32 %0, %1;" : "=f"(r) : "f"(x));
    return r;
}

__device__ __forceinline__ uint32_t f2u(float x) { return __float_as_uint(x); }

__device__ __forceinline__ uint32_t pack_f16(float lo, float hi) {
    __half2 h = __floats2half2_rn(lo, hi);
    return *(uint32_t*)&h;
}

__device__ __forceinline__ void mma8(float* c,
    uint32_t a0, uint32_t a1, uint32_t a2, uint32_t a3,
    uint32_t b0, uint32_t b1)
{
    asm volatile(
        "mma.sync.aligned.m16n8k8.row.col.f32.tf32.tf32.f32 "
        "{%0,%1,%2,%3}, {%4,%5,%6,%7}, {%8,%9}, {%0,%1,%2,%3};"
        : "+f"(c[0]), "+f"(c[1]), "+f"(c[2]), "+f"(c[3])
        : "r"(a0), "r"(a1), "r"(a2), "r"(a3), "r"(b0), "r"(b1));
}

__device__ __forceinline__ void mma16(float* c,
    uint32_t a0, uint32_t a1, uint32_t a2, uint32_t a3,
    uint32_t b0, uint32_t b1)
{
    asm volatile(
        "mma.sync.aligned.m16n8k16.row.col.f32.f16.f16.f32 "
        "{%0,%1,%2,%3}, {%4,%5,%6,%7}, {%8,%9}, {%0,%1,%2,%3};"
        : "+f"(c[0]), "+f"(c[1]), "+f"(c[2]), "+f"(c[3])
        : "r"(a0), "r"(a1), "r"(a2), "r"(a3), "r"(b0), "r"(b1));
}

__device__ __forceinline__ void cp_async16(void* smem_ptr, const void* gptr) {
    uint32_t sa = (uint32_t)__cvta_generic_to_shared(smem_ptr);
    asm volatile("cp.async.cg.shared.global [%0], [%1], 16;" :: "r"(sa), "l"(gptr));
}

// ---------------------------------------------------------------------------
// TF32 GEMM body (proven R7 version). mode: 0=Q/K fp16 natural,
// 2=V fp16 transposed [d][s], 3=fp32 natural (Wo).
// ---------------------------------------------------------------------------
#define GBK 16
#define SA  20
#define SB  136

__device__ __forceinline__ void gemm_body(
    const float* __restrict__ A, const float* __restrict__ W,
    const float* __restrict__ bias,
    float* __restrict__ Cf, __half* __restrict__ Ch,
    int N, int K, int bx, int by, int mode)
{
    __shared__ float As[128 * SA];
    __shared__ float Bs[GBK * SB];

    const int tid = threadIdx.x;
    const int lane = tid & 31;
    const int w = tid >> 5;
    const int wm = (w >> 2) * 64;
    const int wn = (w & 3) * 32;
    const int gid = lane >> 2;
    const int tig = lane & 3;

    const float* Ag = A + (size_t)by * 128 * K;
    const float* Wg = W + bx * 128;

    const int ar  = tid >> 2;
    const int ac4 = (tid & 3) * 4;
    const int br  = tid >> 5;
    const int bc4 = (tid & 31) * 4;

    float4 ra0, ra1, rb0, rb1;

    float acc[4][4][4];
#pragma unroll
    for (int mt = 0; mt < 4; mt++)
#pragma unroll
        for (int nt = 0; nt < 4; nt++)
#pragma unroll
            for (int e = 0; e < 4; e++) acc[mt][nt][e] = 0.f;

#define LOADG(k0) do { \
        ra0 = *(const float4*)(Ag + (size_t)ar * K + (k0) + ac4); \
        ra1 = *(const float4*)(Ag + (size_t)(ar + 64) * K + (k0) + ac4); \
        rb0 = *(const float4*)(Wg + (size_t)((k0) + br) * N + bc4); \
        rb1 = *(const float4*)(Wg + (size_t)((k0) + br + 8) * N + bc4); \
    } while (0)

#define STORES() do { \
        float4 t; \
        t.x = to_tf32(ra0.x); t.y = to_tf32(ra0.y); t.z = to_tf32(ra0.z); t.w = to_tf32(ra0.w); \
        *(float4*)(&As[ar * SA + ac4]) = t; \
        t.x = to_tf32(ra1.x); t.y = to_tf32(ra1.y); t.z = to_tf32(ra1.z); t.w = to_tf32(ra1.w); \
        *(float4*)(&As[(ar + 64) * SA + ac4]) = t; \
        t.x = to_tf32(rb0.x); t.y = to_tf32(rb0.y); t.z = to_tf32(rb0.z); t.w = to_tf32(rb0.w); \
        *(float4*)(&Bs[br * SB + bc4]) = t; \
        t.x = to_tf32(rb1.x); t.y = to_tf32(rb1.y); t.z = to_tf32(rb1.z); t.w = to_tf32(rb1.w); \
        *(float4*)(&Bs[(br + 8) * SB + bc4]) = t; \
    } while (0)

    const int NIT = K / GBK;
    LOADG(0);
    STORES();
    __syncthreads();

    for (int it = 0; it < NIT; it++) {
        if (it + 1 < NIT) LOADG((it + 1) * GBK);

#pragma unroll
        for (int ks = 0; ks < GBK; ks += 8) {
            uint32_t b[4][2];
#pragma unroll
            for (int nt = 0; nt < 4; nt++) {
                b[nt][0] = f2u(Bs[(ks + tig) * SB + wn + nt * 8 + gid]);
                b[nt][1] = f2u(Bs[(ks + tig + 4) * SB + wn + nt * 8 + gid]);
            }
#pragma unroll
            for (int mt = 0; mt < 4; mt++) {
                int r = wm + mt * 16 + gid;
                uint32_t a0 = f2u(As[r * SA + ks + tig]);
                uint32_t a1 = f2u(As[(r + 8) * SA + ks + tig]);
                uint32_t a2 = f2u(As[r * SA + ks + tig + 4]);
                uint32_t a3 = f2u(As[(r + 8) * SA + ks + tig + 4]);
#pragma unroll
                for (int nt = 0; nt < 4; nt++)
                    mma8(acc[mt][nt], a0, a1, a2, a3, b[nt][0], b[nt][1]);
            }
        }
        __syncthreads();
        if (it + 1 < NIT) {
            STORES();
            __syncthreads();
        }
    }

    // epilogue
#pragma unroll
    for (int nt = 0; nt < 4; nt++) {
        int col = bx * 128 + wn + nt * 8 + 2 * tig;
        float b0 = bias[col], b1 = bias[col + 1];
#pragma unroll
        for (int mt = 0; mt < 4; mt++) {
            int row = by * 128 + wm + mt * 16 + gid;
            float c0 = acc[mt][nt][0] + b0;
            float c1 = acc[mt][nt][1] + b1;
            float c2 = acc[mt][nt][2] + b0;
            float c3 = acc[mt][nt][3] + b1;
            if (mode == 3) {
                float2 o;
                o.x = c0; o.y = c1;
                *(float2*)(&Cf[(size_t)row * N + col]) = o;
                o.x = c2; o.y = c3;
                *(float2*)(&Cf[(size_t)(row + 8) * N + col]) = o;
            } else if (mode == 2) {
                // V transposed fp16: VT[col][row], row length = S_LEN
                Ch[(size_t)col * S_LEN + row]           = __float2half_rn(c0);
                Ch[(size_t)(col + 1) * S_LEN + row]     = __float2half_rn(c1);
                Ch[(size_t)col * S_LEN + row + 8]       = __float2half_rn(c2);
                Ch[(size_t)(col + 1) * S_LEN + row + 8] = __float2half_rn(c3);
            } else {
                uint32_t* Cp = (uint32_t*)Ch;
                Cp[(size_t)row * (N / 2) + (col >> 1)]       = pack_f16(c0, c1);
                Cp[(size_t)(row + 8) * (N / 2) + (col >> 1)] = pack_f16(c2, c3);
            }
        }
    }
#undef LOADG
#undef STORES
}

// Fused Q/K/V projection: blockIdx.z selects which projection.
__global__ __launch_bounds__(256) void gemm_qkv(
    const float* __restrict__ q_in, const float* __restrict__ k_in,
    const float* __restrict__ v_in,
    const float* __restrict__ Wq, const float* __restrict__ bq,
    const float* __restrict__ Wk, const float* __restrict__ bk,
    const float* __restrict__ Wv, const float* __restrict__ bv,
    __half* __restrict__ Qo, __half* __restrict__ Ko,
    __half* __restrict__ Vo)
{
    if (blockIdx.z == 0)
        gemm_body(q_in, Wq, bq, nullptr, Qo, DMODEL, DMODEL, blockIdx.x, blockIdx.y, 0);
    else if (blockIdx.z == 1)
        gemm_body(k_in, Wk, bk, nullptr, Ko, DMODEL, DMODEL, blockIdx.x, blockIdx.y, 0);
    else
        gemm_body(v_in, Wv, bv, nullptr, Vo, DMODEL, DMODEL, blockIdx.x, blockIdx.y, 2);
}

__global__ __launch_bounds__(256) void gemm_out(
    const float* __restrict__ A, const float* __restrict__ W,
    const float* __restrict__ bias, float* __restrict__ C)
{
    gemm_body(A, W, bias, C, nullptr, DMODEL, DMODEL, blockIdx.x, blockIdx.y, 3);
}

// ---------------------------------------------------------------------------
// fp16 flash attention + cp.async double-buffered K/V tiles.
// 256 threads, 8 warps, CTA = 128 q-rows; warp owns 16 rows x all 64 cols.
// All operands fp16 (m16n8k16), fp32 accumulate. V pre-transposed [h][d][s].
// ---------------------------------------------------------------------------
#define US 36

__global__ __launch_bounds__(256, 2) void attn_f16(
    const __half* __restrict__ Qh, const __half* __restrict__ Kh,
    const __half* __restrict__ VTh, const int* __restrict__ mask,
    float* __restrict__ O)
{
    extern __shared__ uint32_t smu[];
    uint32_t* QPs = smu;                  // 128*36 u32  (Q staging, then P)
    uint32_t* Ks0 = QPs + 128 * US;       // 64*36
    uint32_t* Vs0 = Ks0 + 64 * US;        // 64*36
    uint32_t* Ks1 = Vs0 + 64 * US;        // 64*36
    uint32_t* Vs1 = Ks1 + 64 * US;        // 64*36
    float*    ms  = (float*)(Vs1 + 64 * US);  // 64

    const int h   = blockIdx.x;
    const int qb  = blockIdx.y;
    const int tid = threadIdx.x;
    const int lane = tid & 31;
    const int w = tid >> 5;
    const int wbase = w * 16;
    const int gid = lane >> 2;
    const int tig = lane & 3;
    const int r0 = wbase + gid;           // owned rows: r0, r0+8

    const float LOG2E = 1.4426950408889634f;
    const float SCALE = 0.125f * LOG2E;

    const uint32_t* Qg = (const uint32_t*)Qh;
    const uint32_t* Kg = (const uint32_t*)Kh;
    const uint32_t* Vg = (const uint32_t*)VTh;

    // loader coordinates for this thread (2 uint4 slots per tile per tensor)
    const int lrow0 = tid >> 3,  lq0 = (tid & 7) * 4;          // slot tid
    const int lrow1 = (256 + tid) >> 3, lq1 = ((256 + tid) & 7) * 4; // slot 256+tid

#define ISSUE_TILE(kb, Kbuf, Vbuf) do { \
        cp_async16(&(Kbuf)[lrow0 * US + lq0], \
            Kg + (size_t)((kb) * 64 + lrow0) * (DMODEL / 2) + h * 32 + lq0); \
        cp_async16(&(Kbuf)[lrow1 * US + lq1], \
            Kg + (size_t)((kb) * 64 + lrow1) * (DMODEL / 2) + h * 32 + lq1); \
        cp_async16(&(Vbuf)[lrow0 * US + lq0], \
            Vg + (size_t)(h * HDIM + lrow0) * (S_LEN / 2) + (kb) * 32 + lq0); \
        cp_async16(&(Vbuf)[lrow1 * US + lq1], \
            Vg + (size_t)(h * HDIM + lrow1) * (S_LEN / 2) + (kb) * 32 + lq1); \
        asm volatile("cp.async.commit_group;"); \
    } while (0)

    // ---- prologue: start tile 0 copy, stage Q ----
    ISSUE_TILE(0, Ks0, Vs0);

#pragma unroll
    for (int it = 0; it < 4; it++) {
        int lin = it * 256 + tid;             // 0..1023 uint4 slots
        int row = lin >> 3, q4 = (lin & 7) * 4;
        *(uint4*)&QPs[row * US + q4] =
            *(const uint4*)(Qg + (size_t)(qb * 128 + row) * (DMODEL / 2) + h * 32 + q4);
    }
    __syncthreads();

    // ---- Hoist Q fragments (4 k16-chunks x 4 regs) ----
    uint32_t q[4][4];
#pragma unroll
    for (int c = 0; c < 4; c++) {
        q[c][0] = QPs[r0 * US + c * 8 + tig];
        q[c][1] = QPs[(r0 + 8) * US + c * 8 + tig];
        q[c][2] = QPs[r0 * US + c * 8 + tig + 4];
        q[c][3] = QPs[(r0 + 8) * US + c * 8 + tig + 4];
    }
    // QPs now reused as P staging; each warp touches only its own 16 rows.

    float o[8][4];
    float m0 = -1e30f, m1 = -1e30f, l0 = 0.f, l1 = 0.f;
#pragma unroll
    for (int nt = 0; nt < 8; nt++)
#pragma unroll
        for (int e = 0; e < 4; e++) o[nt][e] = 0.f;

    const int NT = S_LEN / 64;
    for (int kb = 0; kb < NT; kb++) {
        uint32_t* Kb = (kb & 1) ? Ks1 : Ks0;
        uint32_t* Vb = (kb & 1) ? Vs1 : Vs0;

        if (kb + 1 < NT) {
            if (kb & 1) ISSUE_TILE(kb + 1, Ks0, Vs0);
            else        ISSUE_TILE(kb + 1, Ks1, Vs1);
        }
        if (tid < 64) ms[tid] = (mask[kb * 64 + tid] == 0) ? -1.0e9f * LOG2E : 0.f;

        if (kb + 1 < NT) asm volatile("cp.async.wait_group 1;");
        else             asm volatile("cp.async.wait_group 0;");
        __syncthreads();   // tile kb visible to all warps; ms ready

        // ---- S = Q @ K^T : 16 rows x 64 cols per warp ----
        float s[8][4];
#pragma unroll
        for (int nt = 0; nt < 8; nt++)
#pragma unroll
            for (int e = 0; e < 4; e++) s[nt][e] = 0.f;

#pragma unroll
        for (int c = 0; c < 4; c++) {
#pragma unroll
            for (int nt = 0; nt < 8; nt++) {
                int kr = nt * 8 + gid;
                uint32_t b0 = Kb[kr * US + c * 8 + tig];
                uint32_t b1 = Kb[kr * US + c * 8 + tig + 4];
                mma16(s[nt], q[c][0], q[c][1], q[c][2], q[c][3], b0, b1);
            }
        }

        // ---- warp-local online softmax (log2 domain) ----
        float mx0 = -1e30f, mx1 = -1e30f;
#pragma unroll
        for (int nt = 0; nt < 8; nt++) {
            int col = nt * 8 + 2 * tig;
            float mk0 = ms[col], mk1 = ms[col + 1];
            s[nt][0] = s[nt][0] * SCALE + mk0;
            s[nt][1] = s[nt][1] * SCALE + mk1;
            s[nt][2] = s[nt][2] * SCALE + mk0;
            s[nt][3] = s[nt][3] * SCALE + mk1;
            mx0 = fmaxf(mx0, fmaxf(s[nt][0], s[nt][1]));
            mx1 = fmaxf(mx1, fmaxf(s[nt][2], s[nt][3]));
        }
        mx0 = fmaxf(mx0, __shfl_xor_sync(0xffffffffu, mx0, 1));
        mx0 = fmaxf(mx0, __shfl_xor_sync(0xffffffffu, mx0, 2));
        mx1 = fmaxf(mx1, __shfl_xor_sync(0xffffffffu, mx1, 1));
        mx1 = fmaxf(mx1, __shfl_xor_sync(0xffffffffu, mx1, 2));

        float nm0 = fmaxf(m0, mx0);
        float nm1 = fmaxf(m1, mx1);
        float f0 = exp2f(m0 - nm0);
        float f1 = exp2f(m1 - nm1);
        m0 = nm0; m1 = nm1;

        float sum0 = 0.f, sum1 = 0.f;
#pragma unroll
        for (int nt = 0; nt < 8; nt++) {
            float p0 = exp2f(s[nt][0] - nm0);
            float p1 = exp2f(s[nt][1] - nm0);
            float p2 = exp2f(s[nt][2] - nm1);
            float p3 = exp2f(s[nt][3] - nm1);
            sum0 += p0 + p1; sum1 += p2 + p3;
            QPs[r0 * US + nt * 4 + tig]       = pack_f16(p0, p1);
            QPs[(r0 + 8) * US + nt * 4 + tig] = pack_f16(p2, p3);
            o[nt][0] *= f0; o[nt][1] *= f0;
            o[nt][2] *= f1; o[nt][3] *= f1;
        }
        sum0 += __shfl_xor_sync(0xffffffffu, sum0, 1);
        sum0 += __shfl_xor_sync(0xffffffffu, sum0, 2);
        sum1 += __shfl_xor_sync(0xffffffffu, sum1, 1);
        sum1 += __shfl_xor_sync(0xffffffffu, sum1, 2);
        l0 = l0 * f0 + sum0;
        l1 = l1 * f1 + sum1;
        __syncwarp();   // P rows warp-private: order stores before loads

        // ---- O += P @ V ----
#pragma unroll
        for (int c = 0; c < 4; c++) {
            uint32_t a0 = QPs[r0 * US + c * 8 + tig];
            uint32_t a1 = QPs[(r0 + 8) * US + c * 8 + tig];
            uint32_t a2 = QPs[r0 * US + c * 8 + tig + 4];
            uint32_t a3 = QPs[(r0 + 8) * US + c * 8 + tig + 4];
#pragma unroll
            for (int nt = 0; nt < 8; nt++) {
                int dc = nt * 8 + gid;
                uint32_t b0 = Vb[dc * US + c * 8 + tig];
                uint32_t b1 = Vb[dc * US + c * 8 + tig + 4];
                mma16(o[nt], a0, a1, a2, a3, b0, b1);
            }
        }
        __syncthreads();   // all warps done with Kb/Vb before it's refilled
    }

    // ---- normalize + write fp32 ----
    float inv0 = 1.f / fmaxf(l0, 1e-20f);
    float inv1 = 1.f / fmaxf(l1, 1e-20f);
#pragma unroll
    for (int nt = 0; nt < 8; nt++) {
        int col = h * HDIM + nt * 8 + 2 * tig;
        float2 r;
        r.x = o[nt][0] * inv0; r.y = o[nt][1] * inv0;
        *(float2*)(&O[(size_t)(qb * 128 + r0) * DMODEL + col]) = r;
        r.x = o[nt][2] * inv1; r.y = o[nt][3] * inv1;
        *(float2*)(&O[(size_t)(qb * 128 + r0 + 8) * DMODEL + col]) = r;
    }
#undef ISSUE_TILE
}

// ---------------------------------------------------------------------------
extern "C" void kernel_launch(void* const* d_in, const int* in_sizes, int n_in,
                              void* d_out, int out_size)
{
    (void)in_sizes; (void)n_in; (void)out_size;
    const float* query = (const float*)d_in[0];
    const float* key   = (const float*)d_in[1];
    const float* value = (const float*)d_in[2];
    const int*   amask = (const int*)  d_in[3];
    const float* Wq = (const float*)d_in[4];
    const float* bq = (const float*)d_in[5];
    const float* Wk = (const float*)d_in[6];
    const float* bk = (const float*)d_in[7];
    const float* Wv = (const float*)d_in[8];
    const float* bv = (const float*)d_in[9];
    const float* Wo = (const float*)d_in[10];
    const float* bo = (const float*)d_in[11];
    float* out = (float*)d_out;

    __half *Qhp, *Khp, *VTp;
    float *Ap;
    cudaGetSymbolAddress((void**)&Qhp, g_Qh);
    cudaGetSymbolAddress((void**)&Khp, g_Kh);
    cudaGetSymbolAddress((void**)&VTp, g_VT);
    cudaGetSymbolAddress((void**)&Ap,  g_A);

    // Fused Q/K/V projections (tf32 compute, fp16 output; V pre-transposed)
    gemm_qkv<<<dim3(DMODEL / 128, S_LEN / 128, 3), 256>>>(
        query, key, value, Wq, bq, Wk, bk, Wv, bv, Qhp, Khp, VTp);

    size_t smem = (size_t)(128 * US + 4 * 64 * US) * 4 + 64 * 4;  // ~54.5 KB
    cudaFuncSetAttribute(attn_f16,
                         cudaFuncAttributeMaxDynamicSharedMemorySize, (int)smem);
    attn_f16<<<dim3(NHEADS, S_LEN / 128), 256, smem>>>(Qhp, Khp, VTp, amask, Ap);

    gemm_out<<<dim3(DMODEL / 128, S_LEN / 128), 256>>>(Ap, Wo, bo, out);
}

// round 12
// speedup vs baseline: 1.7506x; 1.2839x over previous
#include <cuda_runtime.h>
#include <cuda_fp16.h>
#include <math.h>
#include <stdint.h>

#define S_LEN   4096
#define DMODEL  1024
#define NHEADS  16
#define HDIM    64

// Scratch (allocation-free rule: device globals)
__device__ __half g_Xq[S_LEN * DMODEL];              // fp16 query input
__device__ __half g_Xk[S_LEN * DMODEL];              // fp16 key input
__device__ __half g_Xv[S_LEN * DMODEL];              // fp16 value input
__device__ __half g_WqT[DMODEL * DMODEL];            // W^T [n][k] fp16
__device__ __half g_WkT[DMODEL * DMODEL];
__device__ __half g_WvT[DMODEL * DMODEL];
__device__ __half g_WoT[DMODEL * DMODEL];
__device__ __half g_Qh[S_LEN * DMODEL];              // [s][d] fp16 projected Q
__device__ __half g_Kh[S_LEN * DMODEL];              // [s][d] fp16 projected K
__device__ __half g_VT[NHEADS * HDIM * S_LEN];       // [h][d][s] fp16 projected V
__device__ __half g_Ah[S_LEN * DMODEL];              // attention out fp16

// ---------------------------------------------------------------------------
// Helpers
// ---------------------------------------------------------------------------
__device__ __forceinline__ uint32_t pack_f16(float lo, float hi) {
    __half2 h = __floats2half2_rn(lo, hi);
    return *(uint32_t*)&h;
}

__device__ __forceinline__ void mma16(float* c,
    uint32_t a0, uint32_t a1, uint32_t a2, uint32_t a3,
    uint32_t b0, uint32_t b1)
{
    asm volatile(
        "mma.sync.aligned.m16n8k16.row.col.f32.f16.f16.f32 "
        "{%0,%1,%2,%3}, {%4,%5,%6,%7}, {%8,%9}, {%0,%1,%2,%3};"
        : "+f"(c[0]), "+f"(c[1]), "+f"(c[2]), "+f"(c[3])
        : "r"(a0), "r"(a1), "r"(a2), "r"(a3), "r"(b0), "r"(b1));
}

__device__ __forceinline__ void cp_async16(void* smem_ptr, const void* gptr) {
    uint32_t sa = (uint32_t)__cvta_generic_to_shared(smem_ptr);
    asm volatile("cp.async.cg.shared.global [%0], [%1], 16;" :: "r"(sa), "l"(gptr));
}

// ---------------------------------------------------------------------------
// Prepass 1: fp32 -> fp16 activations (rn).  grid (4096, 3), 256 thr.
// ---------------------------------------------------------------------------
__global__ __launch_bounds__(256) void cvt_act(
    const float* __restrict__ q, const float* __restrict__ k,
    const float* __restrict__ v,
    __half* __restrict__ qo, __half* __restrict__ ko, __half* __restrict__ vo)
{
    const float* src = (blockIdx.y == 0) ? q : (blockIdx.y == 1) ? k : v;
    __half* dst      = (blockIdx.y == 0) ? qo : (blockIdx.y == 1) ? ko : vo;
    int i = (blockIdx.x * 256 + threadIdx.x) * 4;
    float4 xv = *(const float4*)(src + i);
    uint2 o;
    o.x = pack_f16(xv.x, xv.y);
    o.y = pack_f16(xv.z, xv.w);
    *(uint2*)((uint32_t*)dst + i / 2) = o;
}

// ---------------------------------------------------------------------------
// Prepass 2: weight transpose+convert  W[k][n] fp32 -> WT[n][k] fp16.
// grid (32, 32, 4), 256 thr, 32x32 tiles via smem.
// ---------------------------------------------------------------------------
__global__ __launch_bounds__(256) void wtrans(
    const float* __restrict__ Wq, const float* __restrict__ Wk,
    const float* __restrict__ Wv, const float* __restrict__ Wo,
    __half* __restrict__ WqT, __half* __restrict__ WkT,
    __half* __restrict__ WvT, __half* __restrict__ WoT)
{
    __shared__ float t[32][33];
    const float* W = (blockIdx.z == 0) ? Wq : (blockIdx.z == 1) ? Wk
                   : (blockIdx.z == 2) ? Wv : Wo;
    __half* WT     = (blockIdx.z == 0) ? WqT : (blockIdx.z == 1) ? WkT
                   : (blockIdx.z == 2) ? WvT : WoT;
    int n0 = blockIdx.x * 32, k0 = blockIdx.y * 32;
    int tx = threadIdx.x & 31, ty = threadIdx.x >> 5;   // ty 0..7
#pragma unroll
    for (int i = 0; i < 4; i++) {
        int kl = ty * 4 + i;
        t[tx][kl] = W[(size_t)(k0 + kl) * DMODEL + n0 + tx];
    }
    __syncthreads();
#pragma unroll
    for (int i = 0; i < 4; i++) {
        int nl = ty * 4 + i;
        WT[(size_t)(n0 + nl) * DMODEL + k0 + tx] = __float2half_rn(t[nl][tx]);
    }
}

// ---------------------------------------------------------------------------
// FP16 GEMM: C[M,N] = A[M,K] @ W[K,N] + bias, with A fp16 [m][k] and
// WT fp16 [n][k] (both k-contiguous). cp.async 3-stage, BK=32, one barrier
// per iteration. BM=BN=128, 256 thr, 8 warps 2x4, warp tile 64m x 32n.
// Smem row stride 20 u32 (16 data + 4 pad): gid*20+tig is a bank bijection.
// mode: 0 = fp16 natural out, 2 = fp16 transposed [d][s] out, 3 = fp32 out.
// ---------------------------------------------------------------------------
#define HBK  32
#define HSA  20
#define STG_U (128 * HSA)            // u32 per operand per stage (2560)
#define SMEM_GEMM (3 * 2 * STG_U * 4)  // 61440 bytes

__device__ __forceinline__ void gemm_body(
    const __half* __restrict__ A, const __half* __restrict__ WT,
    const float* __restrict__ bias,
    float* __restrict__ Cf, __half* __restrict__ Ch,
    int N, int K, int bx, int by, int mode)
{
    extern __shared__ uint32_t smu[];

    const int tid = threadIdx.x;
    const int lane = tid & 31;
    const int w = tid >> 5;
    const int wm = (w >> 2) * 64;
    const int wn = (w & 3) * 32;
    const int gid = lane >> 2;
    const int tig = lane & 3;

    const int KU = K / 2;  // u32 per row
    const uint32_t* Agu = (const uint32_t*)(A) + (size_t)by * 128 * KU;
    const uint32_t* Bgu = (const uint32_t*)(WT) + (size_t)bx * 128 * KU;

    // loader chunk coordinates (2 chunks per operand per thread)
    const int c0 = tid,        r0_ = c0 >> 2, kc0 = (c0 & 3) * 4;
    const int c1 = tid + 256,  r1_ = c1 >> 2, kc1 = (c1 & 3) * 4;

    float acc[4][4][4];
#pragma unroll
    for (int mt = 0; mt < 4; mt++)
#pragma unroll
        for (int nt = 0; nt < 4; nt++)
#pragma unroll
            for (int e = 0; e < 4; e++) acc[mt][nt][e] = 0.f;

#define G_ISSUE(k0u, sA, sB) do { \
        cp_async16(&(sA)[r0_ * HSA + kc0], Agu + (size_t)r0_ * KU + (k0u) + kc0); \
        cp_async16(&(sA)[r1_ * HSA + kc1], Agu + (size_t)r1_ * KU + (k0u) + kc1); \
        cp_async16(&(sB)[r0_ * HSA + kc0], Bgu + (size_t)r0_ * KU + (k0u) + kc0); \
        cp_async16(&(sB)[r1_ * HSA + kc1], Bgu + (size_t)r1_ * KU + (k0u) + kc1); \
        asm volatile("cp.async.commit_group;"); \
    } while (0)

    const int NIT = K / HBK;   // 32
    // prologue: stages 0 and 1
    G_ISSUE(0,  smu + 0 * 2 * STG_U, smu + 0 * 2 * STG_U + STG_U);
    G_ISSUE(16, smu + 1 * 2 * STG_U, smu + 1 * 2 * STG_U + STG_U);

    for (int it = 0; it < NIT; it++) {
        if (it + 1 < NIT) asm volatile("cp.async.wait_group 1;");
        else              asm volatile("cp.async.wait_group 0;");
        __syncthreads();

        if (it + 2 < NIT) {
            uint32_t* sA = smu + ((it + 2) % 3) * 2 * STG_U;
            G_ISSUE((it + 2) * 16, sA, sA + STG_U);
        }

        uint32_t* As = smu + (it % 3) * 2 * STG_U;
        uint32_t* Bs = As + STG_U;

#pragma unroll
        for (int ks2 = 0; ks2 < 2; ks2++) {
            int col = ks2 * 8;
            uint32_t b[4][2];
#pragma unroll
            for (int nt = 0; nt < 4; nt++) {
                b[nt][0] = Bs[(wn + nt * 8 + gid) * HSA + col + tig];
                b[nt][1] = Bs[(wn + nt * 8 + gid) * HSA + col + tig + 4];
            }
#pragma unroll
            for (int mt = 0; mt < 4; mt++) {
                int r = wm + mt * 16 + gid;
                uint32_t a0 = As[r * HSA + col + tig];
                uint32_t a1 = As[(r + 8) * HSA + col + tig];
                uint32_t a2 = As[r * HSA + col + tig + 4];
                uint32_t a3 = As[(r + 8) * HSA + col + tig + 4];
#pragma unroll
                for (int nt = 0; nt < 4; nt++)
                    mma16(acc[mt][nt], a0, a1, a2, a3, b[nt][0], b[nt][1]);
            }
        }
        __syncthreads();   // stage (it%3) consumed; safe to refill at it+3
    }

    // epilogue
#pragma unroll
    for (int nt = 0; nt < 4; nt++) {
        int col = bx * 128 + wn + nt * 8 + 2 * tig;
        float b0 = bias[col], b1 = bias[col + 1];
#pragma unroll
        for (int mt = 0; mt < 4; mt++) {
            int row = by * 128 + wm + mt * 16 + gid;
            float c0v = acc[mt][nt][0] + b0;
            float c1v = acc[mt][nt][1] + b1;
            float c2v = acc[mt][nt][2] + b0;
            float c3v = acc[mt][nt][3] + b1;
            if (mode == 3) {
                float2 o;
                o.x = c0v; o.y = c1v;
                *(float2*)(&Cf[(size_t)row * N + col]) = o;
                o.x = c2v; o.y = c3v;
                *(float2*)(&Cf[(size_t)(row + 8) * N + col]) = o;
            } else if (mode == 2) {
                // V transposed fp16: VT[col][row], row length = S_LEN
                Ch[(size_t)col * S_LEN + row]           = __float2half_rn(c0v);
                Ch[(size_t)(col + 1) * S_LEN + row]     = __float2half_rn(c1v);
                Ch[(size_t)col * S_LEN + row + 8]       = __float2half_rn(c2v);
                Ch[(size_t)(col + 1) * S_LEN + row + 8] = __float2half_rn(c3v);
            } else {
                uint32_t* Cp = (uint32_t*)Ch;
                Cp[(size_t)row * (N / 2) + (col >> 1)]       = pack_f16(c0v, c1v);
                Cp[(size_t)(row + 8) * (N / 2) + (col >> 1)] = pack_f16(c2v, c3v);
            }
        }
    }
#undef G_ISSUE
}

// Fused Q/K/V projection: blockIdx.z selects which projection.
__global__ __launch_bounds__(256) void gemm_qkv(
    const __half* __restrict__ xq, const __half* __restrict__ xk,
    const __half* __restrict__ xv,
    const __half* __restrict__ WqT, const float* __restrict__ bq,
    const __half* __restrict__ WkT, const float* __restrict__ bk,
    const __half* __restrict__ WvT, const float* __restrict__ bv,
    __half* __restrict__ Qo, __half* __restrict__ Ko,
    __half* __restrict__ Vo)
{
    if (blockIdx.z == 0)
        gemm_body(xq, WqT, bq, nullptr, Qo, DMODEL, DMODEL, blockIdx.x, blockIdx.y, 0);
    else if (blockIdx.z == 1)
        gemm_body(xk, WkT, bk, nullptr, Ko, DMODEL, DMODEL, blockIdx.x, blockIdx.y, 0);
    else
        gemm_body(xv, WvT, bv, nullptr, Vo, DMODEL, DMODEL, blockIdx.x, blockIdx.y, 2);
}

__global__ __launch_bounds__(256) void gemm_out(
    const __half* __restrict__ A, const __half* __restrict__ WT,
    const float* __restrict__ bias, float* __restrict__ C)
{
    gemm_body(A, WT, bias, C, nullptr, DMODEL, DMODEL, blockIdx.x, blockIdx.y, 3);
}

// ---------------------------------------------------------------------------
// fp16 flash attention + cp.async double-buffered K/V tiles (proven R11).
// 256 threads, 8 warps, CTA = 128 q-rows; warp owns 16 rows x all 64 cols.
// Output written in fp16 (same rounding point R8 proved at 4.07e-4).
// ---------------------------------------------------------------------------
#define US 36

__global__ __launch_bounds__(256, 2) void attn_f16(
    const __half* __restrict__ Qh, const __half* __restrict__ Kh,
    const __half* __restrict__ VTh, const int* __restrict__ mask,
    __half* __restrict__ Oh)
{
    extern __shared__ uint32_t smu[];
    uint32_t* QPs = smu;                  // 128*36 u32  (Q staging, then P)
    uint32_t* Ks0 = QPs + 128 * US;       // 64*36
    uint32_t* Vs0 = Ks0 + 64 * US;        // 64*36
    uint32_t* Ks1 = Vs0 + 64 * US;        // 64*36
    uint32_t* Vs1 = Ks1 + 64 * US;        // 64*36
    float*    ms  = (float*)(Vs1 + 64 * US);  // 64

    const int h   = blockIdx.x;
    const int qb  = blockIdx.y;
    const int tid = threadIdx.x;
    const int lane = tid & 31;
    const int w = tid >> 5;
    const int wbase = w * 16;
    const int gid = lane >> 2;
    const int tig = lane & 3;
    const int r0 = wbase + gid;           // owned rows: r0, r0+8

    const float LOG2E = 1.4426950408889634f;
    const float SCALE = 0.125f * LOG2E;

    const uint32_t* Qg = (const uint32_t*)Qh;
    const uint32_t* Kg = (const uint32_t*)Kh;
    const uint32_t* Vg = (const uint32_t*)VTh;

    const int lrow0 = tid >> 3,  lq0 = (tid & 7) * 4;
    const int lrow1 = (256 + tid) >> 3, lq1 = ((256 + tid) & 7) * 4;

#define ISSUE_TILE(kb, Kbuf, Vbuf) do { \
        cp_async16(&(Kbuf)[lrow0 * US + lq0], \
            Kg + (size_t)((kb) * 64 + lrow0) * (DMODEL / 2) + h * 32 + lq0); \
        cp_async16(&(Kbuf)[lrow1 * US + lq1], \
            Kg + (size_t)((kb) * 64 + lrow1) * (DMODEL / 2) + h * 32 + lq1); \
        cp_async16(&(Vbuf)[lrow0 * US + lq0], \
            Vg + (size_t)(h * HDIM + lrow0) * (S_LEN / 2) + (kb) * 32 + lq0); \
        cp_async16(&(Vbuf)[lrow1 * US + lq1], \
            Vg + (size_t)(h * HDIM + lrow1) * (S_LEN / 2) + (kb) * 32 + lq1); \
        asm volatile("cp.async.commit_group;"); \
    } while (0)

    ISSUE_TILE(0, Ks0, Vs0);

#pragma unroll
    for (int it = 0; it < 4; it++) {
        int lin = it * 256 + tid;
        int row = lin >> 3, q4 = (lin & 7) * 4;
        *(uint4*)&QPs[row * US + q4] =
            *(const uint4*)(Qg + (size_t)(qb * 128 + row) * (DMODEL / 2) + h * 32 + q4);
    }
    __syncthreads();

    uint32_t q[4][4];
#pragma unroll
    for (int c = 0; c < 4; c++) {
        q[c][0] = QPs[r0 * US + c * 8 + tig];
        q[c][1] = QPs[(r0 + 8) * US + c * 8 + tig];
        q[c][2] = QPs[r0 * US + c * 8 + tig + 4];
        q[c][3] = QPs[(r0 + 8) * US + c * 8 + tig + 4];
    }

    float o[8][4];
    float m0 = -1e30f, m1 = -1e30f, l0 = 0.f, l1 = 0.f;
#pragma unroll
    for (int nt = 0; nt < 8; nt++)
#pragma unroll
        for (int e = 0; e < 4; e++) o[nt][e] = 0.f;

    const int NT = S_LEN / 64;
    for (int kb = 0; kb < NT; kb++) {
        uint32_t* Kb = (kb & 1) ? Ks1 : Ks0;
        uint32_t* Vb = (kb & 1) ? Vs1 : Vs0;

        if (kb + 1 < NT) {
            if (kb & 1) ISSUE_TILE(kb + 1, Ks0, Vs0);
            else        ISSUE_TILE(kb + 1, Ks1, Vs1);
        }
        if (tid < 64) ms[tid] = (mask[kb * 64 + tid] == 0) ? -1.0e9f * LOG2E : 0.f;

        if (kb + 1 < NT) asm volatile("cp.async.wait_group 1;");
        else             asm volatile("cp.async.wait_group 0;");
        __syncthreads();

        float s[8][4];
#pragma unroll
        for (int nt = 0; nt < 8; nt++)
#pragma unroll
            for (int e = 0; e < 4; e++) s[nt][e] = 0.f;

#pragma unroll
        for (int c = 0; c < 4; c++) {
#pragma unroll
            for (int nt = 0; nt < 8; nt++) {
                int kr = nt * 8 + gid;
                uint32_t b0 = Kb[kr * US + c * 8 + tig];
                uint32_t b1 = Kb[kr * US + c * 8 + tig + 4];
                mma16(s[nt], q[c][0], q[c][1], q[c][2], q[c][3], b0, b1);
            }
        }

        float mx0 = -1e30f, mx1 = -1e30f;
#pragma unroll
        for (int nt = 0; nt < 8; nt++) {
            int col = nt * 8 + 2 * tig;
            float mk0 = ms[col], mk1 = ms[col + 1];
            s[nt][0] = s[nt][0] * SCALE + mk0;
            s[nt][1] = s[nt][1] * SCALE + mk1;
            s[nt][2] = s[nt][2] * SCALE + mk0;
            s[nt][3] = s[nt][3] * SCALE + mk1;
            mx0 = fmaxf(mx0, fmaxf(s[nt][0], s[nt][1]));
            mx1 = fmaxf(mx1, fmaxf(s[nt][2], s[nt][3]));
        }
        mx0 = fmaxf(mx0, __shfl_xor_sync(0xffffffffu, mx0, 1));
        mx0 = fmaxf(mx0, __shfl_xor_sync(0xffffffffu, mx0, 2));
        mx1 = fmaxf(mx1, __shfl_xor_sync(0xffffffffu, mx1, 1));
        mx1 = fmaxf(mx1, __shfl_xor_sync(0xffffffffu, mx1, 2));

        float nm0 = fmaxf(m0, mx0);
        float nm1 = fmaxf(m1, mx1);
        float f0 = exp2f(m0 - nm0);
        float f1 = exp2f(m1 - nm1);
        m0 = nm0; m1 = nm1;

        float sum0 = 0.f, sum1 = 0.f;
#pragma unroll
        for (int nt = 0; nt < 8; nt++) {
            float p0 = exp2f(s[nt][0] - nm0);
            float p1 = exp2f(s[nt][1] - nm0);
            float p2 = exp2f(s[nt][2] - nm1);
            float p3 = exp2f(s[nt][3] - nm1);
            sum0 += p0 + p1; sum1 += p2 + p3;
            QPs[r0 * US + nt * 4 + tig]       = pack_f16(p0, p1);
            QPs[(r0 + 8) * US + nt * 4 + tig] = pack_f16(p2, p3);
            o[nt][0] *= f0; o[nt][1] *= f0;
            o[nt][2] *= f1; o[nt][3] *= f1;
        }
        sum0 += __shfl_xor_sync(0xffffffffu, sum0, 1);
        sum0 += __shfl_xor_sync(0xffffffffu, sum0, 2);
        sum1 += __shfl_xor_sync(0xffffffffu, sum1, 1);
        sum1 += __shfl_xor_sync(0xffffffffu, sum1, 2);
        l0 = l0 * f0 + sum0;
        l1 = l1 * f1 + sum1;
        __syncwarp();

        // ---- O += P @ V ----
#pragma unroll
        for (int c = 0; c < 4; c++) {
            uint32_t a0 = QPs[r0 * US + c * 8 + tig];
            uint32_t a1 = QPs[(r0 + 8) * US + c * 8 + tig];
            uint32_t a2 = QPs[r0 * US + c * 8 + tig + 4];
            uint32_t a3 = QPs[(r0 + 8) * US + c * 8 + tig + 4];
#pragma unroll
            for (int nt = 0; nt < 8; nt++) {
                int dc = nt * 8 + gid;
                uint32_t b0 = Vb[dc * US + c * 8 + tig];
                uint32_t b1 = Vb[dc * US + c * 8 + tig + 4];
                mma16(o[nt], a0, a1, a2, a3, b0, b1);
            }
        }
        __syncthreads();
    }

    // ---- normalize + write fp16 ----
    float inv0 = 1.f / fmaxf(l0, 1e-20f);
    float inv1 = 1.f / fmaxf(l1, 1e-20f);
    uint32_t* Og = (uint32_t*)Oh;
#pragma unroll
    for (int nt = 0; nt < 8; nt++) {
        int cp = h * 32 + nt * 4 + tig;   // u32 (half-pair) column index
        Og[(size_t)(qb * 128 + r0) * (DMODEL / 2) + cp] =
            pack_f16(o[nt][0] * inv0, o[nt][1] * inv0);
        Og[(size_t)(qb * 128 + r0 + 8) * (DMODEL / 2) + cp] =
            pack_f16(o[nt][2] * inv1, o[nt][3] * inv1);
    }
#undef ISSUE_TILE
}

// ---------------------------------------------------------------------------
extern "C" void kernel_launch(void* const* d_in, const int* in_sizes, int n_in,
                              void* d_out, int out_size)
{
    (void)in_sizes; (void)n_in; (void)out_size;
    const float* query = (const float*)d_in[0];
    const float* key   = (const float*)d_in[1];
    const float* value = (const float*)d_in[2];
    const int*   amask = (const int*)  d_in[3];
    const float* Wq = (const float*)d_in[4];
    const float* bq = (const float*)d_in[5];
    const float* Wk = (const float*)d_in[6];
    const float* bk = (const float*)d_in[7];
    const float* Wv = (const float*)d_in[8];
    const float* bv = (const float*)d_in[9];
    const float* Wo = (const float*)d_in[10];
    const float* bo = (const float*)d_in[11];
    float* out = (float*)d_out;

    __half *Xq, *Xk, *Xv, *WqT, *WkT, *WvT, *WoT, *Qhp, *Khp, *VTp, *Ahp;
    cudaGetSymbolAddress((void**)&Xq,  g_Xq);
    cudaGetSymbolAddress((void**)&Xk,  g_Xk);
    cudaGetSymbolAddress((void**)&Xv,  g_Xv);
    cudaGetSymbolAddress((void**)&WqT, g_WqT);
    cudaGetSymbolAddress((void**)&WkT, g_WkT);
    cudaGetSymbolAddress((void**)&WvT, g_WvT);
    cudaGetSymbolAddress((void**)&WoT, g_WoT);
    cudaGetSymbolAddress((void**)&Qhp, g_Qh);
    cudaGetSymbolAddress((void**)&Khp, g_Kh);
    cudaGetSymbolAddress((void**)&VTp, g_VT);
    cudaGetSymbolAddress((void**)&Ahp, g_Ah);

    // Prepass: convert activations + transpose/convert weights to fp16
    cvt_act<<<dim3(S_LEN * DMODEL / 1024, 3), 256>>>(query, key, value, Xq, Xk, Xv);
    wtrans<<<dim3(DMODEL / 32, DMODEL / 32, 4), 256>>>(
        Wq, Wk, Wv, Wo, WqT, WkT, WvT, WoT);

    // Fused Q/K/V projections (pure fp16 cp.async GEMM; V pre-transposed)
    cudaFuncSetAttribute(gemm_qkv,
                         cudaFuncAttributeMaxDynamicSharedMemorySize, SMEM_GEMM);
    gemm_qkv<<<dim3(DMODEL / 128, S_LEN / 128, 3), 256, SMEM_GEMM>>>(
        Xq, Xk, Xv, WqT, bq, WkT, bk, WvT, bv, Qhp, Khp, VTp);

    size_t smem_attn = (size_t)(128 * US + 4 * 64 * US) * 4 + 64 * 4;  // ~54.5 KB
    cudaFuncSetAttribute(attn_f16,
                         cudaFuncAttributeMaxDynamicSharedMemorySize, (int)smem_attn);
    attn_f16<<<dim3(NHEADS, S_LEN / 128), 256, smem_attn>>>(Qhp, Khp, VTp, amask, Ahp);

    cudaFuncSetAttribute(gemm_out,
                         cudaFuncAttributeMaxDynamicSharedMemorySize, SMEM_GEMM);
    gemm_out<<<dim3(DMODEL / 128, S_LEN / 128), 256, SMEM_GEMM>>>(Ahp, WoT, bo, out);
}

// round 15
// speedup vs baseline: 1.8306x; 1.0457x over previous
#include <cuda_runtime.h>
#include <cuda_fp16.h>
#include <math.h>
#include <stdint.h>

#define S_LEN   4096
#define DMODEL  1024
#define NHEADS  16
#define HDIM    64

// Scratch (allocation-free rule: device globals)
__device__ __half g_Xq[S_LEN * DMODEL];              // fp16 query input
__device__ __half g_Xk[S_LEN * DMODEL];              // fp16 key input
__device__ __half g_Xv[S_LEN * DMODEL];              // fp16 value input
__device__ __half g_WqT[DMODEL * DMODEL];            // W^T [n][k] fp16
__device__ __half g_WkT[DMODEL * DMODEL];
__device__ __half g_WvT[DMODEL * DMODEL];
__device__ __half g_WoT[DMODEL * DMODEL];
__device__ __half g_Qh[S_LEN * DMODEL];              // [s][d] fp16 projected Q
__device__ __half g_Kh[S_LEN * DMODEL];              // [s][d] fp16 projected K
__device__ __half g_VT[NHEADS * HDIM * S_LEN];       // [h][d][s] fp16 projected V
__device__ __half g_Ah[S_LEN * DMODEL];              // attention out fp16

// ---------------------------------------------------------------------------
// Helpers
// ---------------------------------------------------------------------------
__device__ __forceinline__ uint32_t pack_f16(float lo, float hi) {
    __half2 h = __floats2half2_rn(lo, hi);
    return *(uint32_t*)&h;
}

__device__ __forceinline__ void mma16(float* c,
    uint32_t a0, uint32_t a1, uint32_t a2, uint32_t a3,
    uint32_t b0, uint32_t b1)
{
    asm volatile(
        "mma.sync.aligned.m16n8k16.row.col.f32.f16.f16.f32 "
        "{%0,%1,%2,%3}, {%4,%5,%6,%7}, {%8,%9}, {%0,%1,%2,%3};"
        : "+f"(c[0]), "+f"(c[1]), "+f"(c[2]), "+f"(c[3])
        : "r"(a0), "r"(a1), "r"(a2), "r"(a3), "r"(b0), "r"(b1));
}

__device__ __forceinline__ void cp_async16(void* smem_ptr, const void* gptr) {
    uint32_t sa = (uint32_t)__cvta_generic_to_shared(smem_ptr);
    asm volatile("cp.async.cg.shared.global [%0], [%1], 16;" :: "r"(sa), "l"(gptr));
}

// ---------------------------------------------------------------------------
// Prepass 1: fp32 -> fp16 activations (rn).  grid (4096, 3), 256 thr.
// ---------------------------------------------------------------------------
__global__ __launch_bounds__(256) void cvt_act(
    const float* __restrict__ q, const float* __restrict__ k,
    const float* __restrict__ v,
    __half* __restrict__ qo, __half* __restrict__ ko, __half* __restrict__ vo)
{
    const float* src = (blockIdx.y == 0) ? q : (blockIdx.y == 1) ? k : v;
    __half* dst      = (blockIdx.y == 0) ? qo : (blockIdx.y == 1) ? ko : vo;
    int i = (blockIdx.x * 256 + threadIdx.x) * 4;
    float4 xv = *(const float4*)(src + i);
    uint2 o;
    o.x = pack_f16(xv.x, xv.y);
    o.y = pack_f16(xv.z, xv.w);
    *(uint2*)((uint32_t*)dst + i / 2) = o;
}

// ---------------------------------------------------------------------------
// Prepass 2: weight transpose+convert  W[k][n] fp32 -> WT[n][k] fp16.
// grid (32, 32, 4), 256 thr, 32x32 tiles via smem.
// ---------------------------------------------------------------------------
__global__ __launch_bounds__(256) void wtrans(
    const float* __restrict__ Wq, const float* __restrict__ Wk,
    const float* __restrict__ Wv, const float* __restrict__ Wo,
    __half* __restrict__ WqT, __half* __restrict__ WkT,
    __half* __restrict__ WvT, __half* __restrict__ WoT)
{
    __shared__ float t[32][33];
    const float* W = (blockIdx.z == 0) ? Wq : (blockIdx.z == 1) ? Wk
                   : (blockIdx.z == 2) ? Wv : Wo;
    __half* WT     = (blockIdx.z == 0) ? WqT : (blockIdx.z == 1) ? WkT
                   : (blockIdx.z == 2) ? WvT : WoT;
    int n0 = blockIdx.x * 32, k0 = blockIdx.y * 32;
    int tx = threadIdx.x & 31, ty = threadIdx.x >> 5;   // ty 0..7
#pragma unroll
    for (int i = 0; i < 4; i++) {
        int kl = ty * 4 + i;
        t[tx][kl] = W[(size_t)(k0 + kl) * DMODEL + n0 + tx];
    }
    __syncthreads();
#pragma unroll
    for (int i = 0; i < 4; i++) {
        int nl = ty * 4 + i;
        WT[(size_t)(n0 + nl) * DMODEL + k0 + tx] = __float2half_rn(t[nl][tx]);
    }
}

// ---------------------------------------------------------------------------
// FP16 GEMM: C[M,N] = A[M,K] @ W[K,N] + bias, with A fp16 [m][k] and
// WT fp16 [n][k] (both k-contiguous). cp.async 3-stage, BK=32, one barrier
// per iteration. BM=BN=128, 256 thr, 8 warps 2x4, warp tile 64m x 32n.
// mode: 0 = fp16 natural out, 2 = fp16 transposed [d][s] out, 3 = fp32 out.
// ---------------------------------------------------------------------------
#define HBK  32
#define HSA  20
#define STG_U (128 * HSA)              // u32 per operand per stage (2560)
#define SMEM_GEMM (3 * 2 * STG_U * 4)  // 61440 bytes

__device__ __forceinline__ void gemm_body(
    const __half* __restrict__ A, const __half* __restrict__ WT,
    const float* __restrict__ bias,
    float* __restrict__ Cf, __half* __restrict__ Ch,
    int N, int K, int bx, int by, int mode)
{
    extern __shared__ uint32_t smu[];

    const int tid = threadIdx.x;
    const int lane = tid & 31;
    const int w = tid >> 5;
    const int wm = (w >> 2) * 64;
    const int wn = (w & 3) * 32;
    const int gid = lane >> 2;
    const int tig = lane & 3;

    const int KU = K / 2;  // u32 per row
    const uint32_t* Agu = (const uint32_t*)(A) + (size_t)by * 128 * KU;
    const uint32_t* Bgu = (const uint32_t*)(WT) + (size_t)bx * 128 * KU;

    const int c0 = tid,        r0_ = c0 >> 2, kc0 = (c0 & 3) * 4;
    const int c1 = tid + 256,  r1_ = c1 >> 2, kc1 = (c1 & 3) * 4;

    float acc[4][4][4];
#pragma unroll
    for (int mt = 0; mt < 4; mt++)
#pragma unroll
        for (int nt = 0; nt < 4; nt++)
#pragma unroll
            for (int e = 0; e < 4; e++) acc[mt][nt][e] = 0.f;

#define G_ISSUE(k0u, sA, sB) do { \
        cp_async16(&(sA)[r0_ * HSA + kc0], Agu + (size_t)r0_ * KU + (k0u) + kc0); \
        cp_async16(&(sA)[r1_ * HSA + kc1], Agu + (size_t)r1_ * KU + (k0u) + kc1); \
        cp_async16(&(sB)[r0_ * HSA + kc0], Bgu + (size_t)r0_ * KU + (k0u) + kc0); \
        cp_async16(&(sB)[r1_ * HSA + kc1], Bgu + (size_t)r1_ * KU + (k0u) + kc1); \
        asm volatile("cp.async.commit_group;"); \
    } while (0)

    const int NIT = K / HBK;
    G_ISSUE(0,  smu + 0 * 2 * STG_U, smu + 0 * 2 * STG_U + STG_U);
    G_ISSUE(16, smu + 1 * 2 * STG_U, smu + 1 * 2 * STG_U + STG_U);

    for (int it = 0; it < NIT; it++) {
        if (it + 1 < NIT) asm volatile("cp.async.wait_group 1;");
        else              asm volatile("cp.async.wait_group 0;");
        __syncthreads();

        if (it + 2 < NIT) {
            uint32_t* sA = smu + ((it + 2) % 3) * 2 * STG_U;
            G_ISSUE((it + 2) * 16, sA, sA + STG_U);
        }

        uint32_t* As = smu + (it % 3) * 2 * STG_U;
        uint32_t* Bs = As + STG_U;

#pragma unroll
        for (int ks2 = 0; ks2 < 2; ks2++) {
            int col = ks2 * 8;
            uint32_t b[4][2];
#pragma unroll
            for (int nt = 0; nt < 4; nt++) {
                b[nt][0] = Bs[(wn + nt * 8 + gid) * HSA + col + tig];
                b[nt][1] = Bs[(wn + nt * 8 + gid) * HSA + col + tig + 4];
            }
#pragma unroll
            for (int mt = 0; mt < 4; mt++) {
                int r = wm + mt * 16 + gid;
                uint32_t a0 = As[r * HSA + col + tig];
                uint32_t a1 = As[(r + 8) * HSA + col + tig];
                uint32_t a2 = As[r * HSA + col + tig + 4];
                uint32_t a3 = As[(r + 8) * HSA + col + tig + 4];
#pragma unroll
                for (int nt = 0; nt < 4; nt++)
                    mma16(acc[mt][nt], a0, a1, a2, a3, b[nt][0], b[nt][1]);
            }
        }
        __syncthreads();
    }

    // epilogue
#pragma unroll
    for (int nt = 0; nt < 4; nt++) {
        int col = bx * 128 + wn + nt * 8 + 2 * tig;
        float b0 = bias[col], b1 = bias[col + 1];
#pragma unroll
        for (int mt = 0; mt < 4; mt++) {
            int row = by * 128 + wm + mt * 16 + gid;
            float c0v = acc[mt][nt][0] + b0;
            float c1v = acc[mt][nt][1] + b1;
            float c2v = acc[mt][nt][2] + b0;
            float c3v = acc[mt][nt][3] + b1;
            if (mode == 3) {
                float2 o;
                o.x = c0v; o.y = c1v;
                *(float2*)(&Cf[(size_t)row * N + col]) = o;
                o.x = c2v; o.y = c3v;
                *(float2*)(&Cf[(size_t)(row + 8) * N + col]) = o;
            } else if (mode == 2) {
                Ch[(size_t)col * S_LEN + row]           = __float2half_rn(c0v);
                Ch[(size_t)(col + 1) * S_LEN + row]     = __float2half_rn(c1v);
                Ch[(size_t)col * S_LEN + row + 8]       = __float2half_rn(c2v);
                Ch[(size_t)(col + 1) * S_LEN + row + 8] = __float2half_rn(c3v);
            } else {
                uint32_t* Cp = (uint32_t*)Ch;
                Cp[(size_t)row * (N / 2) + (col >> 1)]       = pack_f16(c0v, c1v);
                Cp[(size_t)(row + 8) * (N / 2) + (col >> 1)] = pack_f16(c2v, c3v);
            }
        }
    }
#undef G_ISSUE
}

// Fused Q/K/V projection: blockIdx.z selects which projection.
__global__ __launch_bounds__(256) void gemm_qkv(
    const __half* __restrict__ xq, const __half* __restrict__ xk,
    const __half* __restrict__ xv,
    const __half* __restrict__ WqT, const float* __restrict__ bq,
    const __half* __restrict__ WkT, const float* __restrict__ bk,
    const __half* __restrict__ WvT, const float* __restrict__ bv,
    __half* __restrict__ Qo, __half* __restrict__ Ko,
    __half* __restrict__ Vo)
{
    if (blockIdx.z == 0)
        gemm_body(xq, WqT, bq, nullptr, Qo, DMODEL, DMODEL, blockIdx.x, blockIdx.y, 0);
    else if (blockIdx.z == 1)
        gemm_body(xk, WkT, bk, nullptr, Ko, DMODEL, DMODEL, blockIdx.x, blockIdx.y, 0);
    else
        gemm_body(xv, WvT, bv, nullptr, Vo, DMODEL, DMODEL, blockIdx.x, blockIdx.y, 2);
}

__global__ __launch_bounds__(256) void gemm_out(
    const __half* __restrict__ A, const __half* __restrict__ WT,
    const float* __restrict__ bias, float* __restrict__ C)
{
    gemm_body(A, WT, bias, C, nullptr, DMODEL, DMODEL, blockIdx.x, blockIdx.y, 3);
}

// ---------------------------------------------------------------------------
// fp16 flash attention, register-resident P (no smem staging for P),
// cp.async double-buffered K/V tiles, conditional O-rescale.
// 256 threads, 8 warps, CTA = 128 q-rows; warp owns 16 rows x all 64 cols.
// S-accumulator fragments ARE the PV A-operand fragments for this mapping:
//   a[c][0]=pack(p[2c][0],p[2c][1])   a[c][1]=pack(p[2c][2],p[2c][3])
//   a[c][2]=pack(p[2c+1][0],p[2c+1][1]) a[c][3]=pack(p[2c+1][2],p[2c+1][3])
// ---------------------------------------------------------------------------
#define US 36

__global__ __launch_bounds__(256, 2) void attn_f16(
    const __half* __restrict__ Qh, const __half* __restrict__ Kh,
    const __half* __restrict__ VTh, const int* __restrict__ mask,
    __half* __restrict__ Oh)
{
    extern __shared__ uint32_t smu[];
    uint32_t* Qs  = smu;                  // 128*36 u32  (Q staging only)
    uint32_t* Ks0 = Qs + 128 * US;        // 64*36
    uint32_t* Vs0 = Ks0 + 64 * US;        // 64*36
    uint32_t* Ks1 = Vs0 + 64 * US;        // 64*36
    uint32_t* Vs1 = Ks1 + 64 * US;        // 64*36
    float*    ms  = (float*)(Vs1 + 64 * US);  // 64

    const int h   = blockIdx.x;
    const int qb  = blockIdx.y;
    const int tid = threadIdx.x;
    const int lane = tid & 31;
    const int w = tid >> 5;
    const int wbase = w * 16;
    const int gid = lane >> 2;
    const int tig = lane & 3;
    const int r0 = wbase + gid;           // owned rows: r0, r0+8

    const float LOG2E = 1.4426950408889634f;
    const float SCALE = 0.125f * LOG2E;

    const uint32_t* Qg = (const uint32_t*)Qh;
    const uint32_t* Kg = (const uint32_t*)Kh;
    const uint32_t* Vg = (const uint32_t*)VTh;

    const int lrow0 = tid >> 3,  lq0 = (tid & 7) * 4;
    const int lrow1 = (256 + tid) >> 3, lq1 = ((256 + tid) & 7) * 4;

#define ISSUE_TILE(kb, Kbuf, Vbuf) do { \
        cp_async16(&(Kbuf)[lrow0 * US + lq0], \
            Kg + (size_t)((kb) * 64 + lrow0) * (DMODEL / 2) + h * 32 + lq0); \
        cp_async16(&(Kbuf)[lrow1 * US + lq1], \
            Kg + (size_t)((kb) * 64 + lrow1) * (DMODEL / 2) + h * 32 + lq1); \
        cp_async16(&(Vbuf)[lrow0 * US + lq0], \
            Vg + (size_t)(h * HDIM + lrow0) * (S_LEN / 2) + (kb) * 32 + lq0); \
        cp_async16(&(Vbuf)[lrow1 * US + lq1], \
            Vg + (size_t)(h * HDIM + lrow1) * (S_LEN / 2) + (kb) * 32 + lq1); \
        asm volatile("cp.async.commit_group;"); \
    } while (0)

    ISSUE_TILE(0, Ks0, Vs0);

#pragma unroll
    for (int it = 0; it < 4; it++) {
        int lin = it * 256 + tid;
        int row = lin >> 3, q4 = (lin & 7) * 4;
        *(uint4*)&Qs[row * US + q4] =
            *(const uint4*)(Qg + (size_t)(qb * 128 + row) * (DMODEL / 2) + h * 32 + q4);
    }
    __syncthreads();

    uint32_t q[4][4];
#pragma unroll
    for (int c = 0; c < 4; c++) {
        q[c][0] = Qs[r0 * US + c * 8 + tig];
        q[c][1] = Qs[(r0 + 8) * US + c * 8 + tig];
        q[c][2] = Qs[r0 * US + c * 8 + tig + 4];
        q[c][3] = Qs[(r0 + 8) * US + c * 8 + tig + 4];
    }

    float o[8][4];
    float m0 = -1e30f, m1 = -1e30f, l0 = 0.f, l1 = 0.f;
#pragma unroll
    for (int nt = 0; nt < 8; nt++)
#pragma unroll
        for (int e = 0; e < 4; e++) o[nt][e] = 0.f;

    const int NT = S_LEN / 64;
    for (int kb = 0; kb < NT; kb++) {
        uint32_t* Kb = (kb & 1) ? Ks1 : Ks0;
        uint32_t* Vb = (kb & 1) ? Vs1 : Vs0;

        if (kb + 1 < NT) {
            if (kb & 1) ISSUE_TILE(kb + 1, Ks0, Vs0);
            else        ISSUE_TILE(kb + 1, Ks1, Vs1);
        }
        if (tid < 64) ms[tid] = (mask[kb * 64 + tid] == 0) ? -1.0e9f * LOG2E : 0.f;

        if (kb + 1 < NT) asm volatile("cp.async.wait_group 1;");
        else             asm volatile("cp.async.wait_group 0;");
        __syncthreads();   // tile kb visible; ms ready

        // ---- S = Q @ K^T : 16 rows x 64 cols per warp ----
        float s[8][4];
#pragma unroll
        for (int nt = 0; nt < 8; nt++)
#pragma unroll
            for (int e = 0; e < 4; e++) s[nt][e] = 0.f;

#pragma unroll
        for (int c = 0; c < 4; c++) {
#pragma unroll
            for (int nt = 0; nt < 8; nt++) {
                int kr = nt * 8 + gid;
                uint32_t b0 = Kb[kr * US + c * 8 + tig];
                uint32_t b1 = Kb[kr * US + c * 8 + tig + 4];
                mma16(s[nt], q[c][0], q[c][1], q[c][2], q[c][3], b0, b1);
            }
        }

        // ---- warp-local online softmax (log2 domain) ----
        float mx0 = -1e30f, mx1 = -1e30f;
#pragma unroll
        for (int nt = 0; nt < 8; nt++) {
            int col = nt * 8 + 2 * tig;
            float mk0 = ms[col], mk1 = ms[col + 1];
            s[nt][0] = s[nt][0] * SCALE + mk0;
            s[nt][1] = s[nt][1] * SCALE + mk1;
            s[nt][2] = s[nt][2] * SCALE + mk0;
            s[nt][3] = s[nt][3] * SCALE + mk1;
            mx0 = fmaxf(mx0, fmaxf(s[nt][0], s[nt][1]));
            mx1 = fmaxf(mx1, fmaxf(s[nt][2], s[nt][3]));
        }
        mx0 = fmaxf(mx0, __shfl_xor_sync(0xffffffffu, mx0, 1));
        mx0 = fmaxf(mx0, __shfl_xor_sync(0xffffffffu, mx0, 2));
        mx1 = fmaxf(mx1, __shfl_xor_sync(0xffffffffu, mx1, 1));
        mx1 = fmaxf(mx1, __shfl_xor_sync(0xffffffffu, mx1, 2));

        bool need = (mx0 > m0) || (mx1 > m1);
        float nm0 = fmaxf(m0, mx0);
        float nm1 = fmaxf(m1, mx1);
        float f0 = exp2f(m0 - nm0);
        float f1 = exp2f(m1 - nm1);
        m0 = nm0; m1 = nm1;

        // p = exp2(s - m), pack DIRECTLY into PV A-operand fragments
        uint32_t a[4][4];
        float sum0 = 0.f, sum1 = 0.f;
#pragma unroll
        for (int nt = 0; nt < 8; nt++) {
            float p0 = exp2f(s[nt][0] - nm0);
            float p1 = exp2f(s[nt][1] - nm0);
            float p2 = exp2f(s[nt][2] - nm1);
            float p3 = exp2f(s[nt][3] - nm1);
            sum0 += p0 + p1; sum1 += p2 + p3;
            int c = nt >> 1;
            if ((nt & 1) == 0) {
                a[c][0] = pack_f16(p0, p1);
                a[c][1] = pack_f16(p2, p3);
            } else {
                a[c][2] = pack_f16(p0, p1);
                a[c][3] = pack_f16(p2, p3);
            }
        }
        sum0 += __shfl_xor_sync(0xffffffffu, sum0, 1);
        sum0 += __shfl_xor_sync(0xffffffffu, sum0, 2);
        sum1 += __shfl_xor_sync(0xffffffffu, sum1, 1);
        sum1 += __shfl_xor_sync(0xffffffffu, sum1, 2);
        l0 = l0 * f0 + sum0;
        l1 = l1 * f1 + sum1;

        // rescale O only when a new max appeared anywhere in the warp
        if (__any_sync(0xffffffffu, need)) {
#pragma unroll
            for (int nt = 0; nt < 8; nt++) {
                o[nt][0] *= f0; o[nt][1] *= f0;
                o[nt][2] *= f1; o[nt][3] *= f1;
            }
        }

        // ---- O += P @ V (P fragments register-resident) ----
#pragma unroll
        for (int c = 0; c < 4; c++) {
#pragma unroll
            for (int nt = 0; nt < 8; nt++) {
                int dc = nt * 8 + gid;
                uint32_t b0 = Vb[dc * US + c * 8 + tig];
                uint32_t b1 = Vb[dc * US + c * 8 + tig + 4];
                mma16(o[nt], a[c][0], a[c][1], a[c][2], a[c][3], b0, b1);
            }
        }
        __syncthreads();   // all warps done with Kb/Vb before it's refilled
    }

    // ---- normalize + write fp16 ----
    float inv0 = 1.f / fmaxf(l0, 1e-20f);
    float inv1 = 1.f / fmaxf(l1, 1e-20f);
    uint32_t* Og = (uint32_t*)Oh;
#pragma unroll
    for (int nt = 0; nt < 8; nt++) {
        int cp = h * 32 + nt * 4 + tig;   // u32 (half-pair) column index
        Og[(size_t)(qb * 128 + r0) * (DMODEL / 2) + cp] =
            pack_f16(o[nt][0] * inv0, o[nt][1] * inv0);
        Og[(size_t)(qb * 128 + r0 + 8) * (DMODEL / 2) + cp] =
            pack_f16(o[nt][2] * inv1, o[nt][3] * inv1);
    }
#undef ISSUE_TILE
}

// ---------------------------------------------------------------------------
extern "C" void kernel_launch(void* const* d_in, const int* in_sizes, int n_in,
                              void* d_out, int out_size)
{
    (void)in_sizes; (void)n_in; (void)out_size;
    const float* query = (const float*)d_in[0];
    const float* key   = (const float*)d_in[1];
    const float* value = (const float*)d_in[2];
    const int*   amask = (const int*)  d_in[3];
    const float* Wq = (const float*)d_in[4];
    const float* bq = (const float*)d_in[5];
    const float* Wk = (const float*)d_in[6];
    const float* bk = (const float*)d_in[7];
    const float* Wv = (const float*)d_in[8];
    const float* bv = (const float*)d_in[9];
    const float* Wo = (const float*)d_in[10];
    const float* bo = (const float*)d_in[11];
    float* out = (float*)d_out;

    __half *Xq, *Xk, *Xv, *WqT, *WkT, *WvT, *WoT, *Qhp, *Khp, *VTp, *Ahp;
    cudaGetSymbolAddress((void**)&Xq,  g_Xq);
    cudaGetSymbolAddress((void**)&Xk,  g_Xk);
    cudaGetSymbolAddress((void**)&Xv,  g_Xv);
    cudaGetSymbolAddress((void**)&WqT, g_WqT);
    cudaGetSymbolAddress((void**)&WkT, g_WkT);
    cudaGetSymbolAddress((void**)&WvT, g_WvT);
    cudaGetSymbolAddress((void**)&WoT, g_WoT);
    cudaGetSymbolAddress((void**)&Qhp, g_Qh);
    cudaGetSymbolAddress((void**)&Khp, g_Kh);
    cudaGetSymbolAddress((void**)&VTp, g_VT);
    cudaGetSymbolAddress((void**)&Ahp, g_Ah);

    // Prepass: convert activations + transpose/convert weights to fp16
    cvt_act<<<dim3(S_LEN * DMODEL / 1024, 3), 256>>>(query, key, value, Xq, Xk, Xv);
    wtrans<<<dim3(DMODEL / 32, DMODEL / 32, 4), 256>>>(
        Wq, Wk, Wv, Wo, WqT, WkT, WvT, WoT);

    // Fused Q/K/V projections (pure fp16 cp.async GEMM; V pre-transposed)
    cudaFuncSetAttribute(gemm_qkv,
                         cudaFuncAttributeMaxDynamicSharedMemorySize, SMEM_GEMM);
    gemm_qkv<<<dim3(DMODEL / 128, S_LEN / 128, 3), 256, SMEM_GEMM>>>(
        Xq, Xk, Xv, WqT, bq, WkT, bk, WvT, bv, Qhp, Khp, VTp);

    size_t smem_attn = (size_t)(128 * US + 4 * 64 * US) * 4 + 64 * 4;  // ~54.5 KB
    cudaFuncSetAttribute(attn_f16,
                         cudaFuncAttributeMaxDynamicSharedMemorySize, (int)smem_attn);
    attn_f16<<<dim3(NHEADS, S_LEN / 128), 256, smem_attn>>>(Qhp, Khp, VTp, amask, Ahp);

    cudaFuncSetAttribute(gemm_out,
                         cudaFuncAttributeMaxDynamicSharedMemorySize, SMEM_GEMM);
    gemm_out<<<dim3(DMODEL / 128, S_LEN / 128), 256, SMEM_GEMM>>>(Ahp, WoT, bo, out);
}